// round 3
// baseline (speedup 1.0000x reference)
#include <cuda_runtime.h>

#define T_DIM 4096
#define B_DIM 4
#define D_DIM 1024
#define H_DIM 4096
#define M_TOT (T_DIM * B_DIM)   // 16384

#define MT 128                  // M tile per block
#define NT 128                  // N tile per chunk
#define KC 16                   // K chunk
#define KB_ITERS (D_DIM / KC)   // 64
#define NCHUNK 8                // 8 * 128 = 1024 N-cols per block

// Scratch (static __device__: allocation-free per harness rules)
__device__ float g_part[8][M_TOT];  // [mlp*4 + quarter][m] partial logits
__device__ float g_x[M_TOT];        // boundary logits (scan input)
__device__ int   g_rm[M_TOT];       // reset mask

__device__ __forceinline__ unsigned long long pack2(float x) {
    unsigned long long r;
    asm("mov.b64 %0, {%1, %2};" : "=l"(r) : "f"(x), "f"(x));
    return r;
}
__device__ __forceinline__ void fma2(unsigned long long& d,
                                     unsigned long long a,
                                     unsigned long long b) {
    asm("fma.rn.f32x2 %0, %1, %2, %0;" : "+l"(d) : "l"(a), "l"(b));
}
__device__ __forceinline__ float2 unpack2(unsigned long long v) {
    float lo, hi;
    asm("mov.b64 {%0, %1}, %2;" : "=f"(lo), "=f"(hi) : "l"(v));
    return make_float2(lo, hi);
}

__global__ void __launch_bounds__(256, 2)
mlp_gemm_kernel(const float* __restrict__ X,
                const float* __restrict__ Wb1, const float* __restrict__ bb1,
                const float* __restrict__ Wb2,
                const float* __restrict__ Wr1, const float* __restrict__ br1,
                const float* __restrict__ Wr2)
{
    __shared__ __align__(16) float Xs[2][KC * MT];
    __shared__ __align__(16) float Ws[2][KC * NT];
    __shared__ __align__(16) float red[MT][17];   // padded: no bank conflicts

    const int tid   = threadIdx.x;
    const int mBase = blockIdx.x * MT;
    const int yy    = blockIdx.y;      // 0..7: {mlp, quarter}
    const int mlp   = yy >> 2;
    const int q     = yy & 3;

    const float* __restrict__ W1 = mlp ? Wr1 : Wb1;
    const float* __restrict__ b1 = mlp ? br1 : bb1;
    const float* __restrict__ w2 = mlp ? Wr2 : Wb2;

    // warp tiling: 8 warps = 4 (M) x 2 (N); warp tile = 32 rows x 64 cols
    const int wid  = tid >> 5;
    const int lane = tid & 31;
    const int wm   = wid & 3;
    const int wn   = wid >> 2;
    const int lm   = lane & 3;
    const int ln   = lane >> 2;
    const int rowOff = wm * 32 + lm * 8;   // 8 rows per thread
    const int colOff = wn * 64 + ln * 8;   // 8 cols per thread

    // global-load assignments
    const int xRow = tid >> 1;             // 0..127
    const int xK0  = (tid & 1) * 8;        // k offset 0 or 8
    const int wK0  = tid >> 5;             // 0..7
    const int wCol = (tid & 31) * 4;

    const float* __restrict__ Xg = X + (size_t)mBase * D_DIM;

    float rowAcc = 0.f;                    // valid for tid < 128

    for (int nc = 0; nc < NCHUNK; ++nc) {
        const int nBase = q * 1024 + nc * NT;
        const float* __restrict__ Wg = W1 + nBase;

        unsigned long long acc[8][4];
        #pragma unroll
        for (int r = 0; r < 8; ++r)
            #pragma unroll
            for (int c = 0; c < 4; ++c) acc[r][c] = 0ULL;

        // prologue: fetch kb=0, stage into buffer 0
        float4 xv0 = *(const float4*)&Xg[xRow * D_DIM + xK0];
        float4 xv1 = *(const float4*)&Xg[xRow * D_DIM + xK0 + 4];
        float4 wv0 = *(const float4*)&Wg[(size_t)(wK0)     * H_DIM + wCol];
        float4 wv1 = *(const float4*)&Wg[(size_t)(wK0 + 8) * H_DIM + wCol];
        {
            float* xs = Xs[0];
            xs[(xK0 + 0) * MT + xRow] = xv0.x;
            xs[(xK0 + 1) * MT + xRow] = xv0.y;
            xs[(xK0 + 2) * MT + xRow] = xv0.z;
            xs[(xK0 + 3) * MT + xRow] = xv0.w;
            xs[(xK0 + 4) * MT + xRow] = xv1.x;
            xs[(xK0 + 5) * MT + xRow] = xv1.y;
            xs[(xK0 + 6) * MT + xRow] = xv1.z;
            xs[(xK0 + 7) * MT + xRow] = xv1.w;
            *(float4*)&Ws[0][(wK0)     * NT + wCol] = wv0;
            *(float4*)&Ws[0][(wK0 + 8) * NT + wCol] = wv1;
        }
        __syncthreads();

        for (int kb = 0; kb < KB_ITERS; ++kb) {
            const int cur = kb & 1;
            if (kb + 1 < KB_ITERS) {        // issue next tile's LDGs early
                const int kn = (kb + 1) * KC;
                xv0 = *(const float4*)&Xg[xRow * D_DIM + kn + xK0];
                xv1 = *(const float4*)&Xg[xRow * D_DIM + kn + xK0 + 4];
                wv0 = *(const float4*)&Wg[(size_t)(kn + wK0)     * H_DIM + wCol];
                wv1 = *(const float4*)&Wg[(size_t)(kn + wK0 + 8) * H_DIM + wCol];
            }

            const float* xs = Xs[cur];
            const float* ws = Ws[cur];
            #pragma unroll
            for (int k = 0; k < KC; ++k) {
                float4 a0 = *(const float4*)&xs[k * MT + rowOff];
                float4 a1 = *(const float4*)&xs[k * MT + rowOff + 4];
                ulonglong2 bq0 = *(const ulonglong2*)&ws[k * NT + colOff];
                ulonglong2 bq1 = *(const ulonglong2*)&ws[k * NT + colOff + 4];
                unsigned long long bp0 = bq0.x, bp1 = bq0.y, bp2 = bq1.x, bp3 = bq1.y;
                float a[8] = {a0.x, a0.y, a0.z, a0.w, a1.x, a1.y, a1.z, a1.w};
                #pragma unroll
                for (int r = 0; r < 8; ++r) {
                    unsigned long long ap = pack2(a[r]);
                    fma2(acc[r][0], ap, bp0);
                    fma2(acc[r][1], ap, bp1);
                    fma2(acc[r][2], ap, bp2);
                    fma2(acc[r][3], ap, bp3);
                }
            }

            if (kb + 1 < KB_ITERS) {        // stage next tile
                float* xs2 = Xs[cur ^ 1];
                xs2[(xK0 + 0) * MT + xRow] = xv0.x;
                xs2[(xK0 + 1) * MT + xRow] = xv0.y;
                xs2[(xK0 + 2) * MT + xRow] = xv0.z;
                xs2[(xK0 + 3) * MT + xRow] = xv0.w;
                xs2[(xK0 + 4) * MT + xRow] = xv1.x;
                xs2[(xK0 + 5) * MT + xRow] = xv1.y;
                xs2[(xK0 + 6) * MT + xRow] = xv1.z;
                xs2[(xK0 + 7) * MT + xRow] = xv1.w;
                *(float4*)&Ws[cur ^ 1][(wK0)     * NT + wCol] = wv0;
                *(float4*)&Ws[cur ^ 1][(wK0 + 8) * NT + wCol] = wv1;
            }
            __syncthreads();
        }

        // epilogue: ReLU + dot(w2), deterministic tree reduce across 16 col-threads
        #pragma unroll
        for (int r = 0; r < 8; ++r) {
            float s = 0.f;
            #pragma unroll
            for (int c = 0; c < 4; ++c) {
                float2 v = unpack2(acc[r][c]);
                int n0 = nBase + colOff + c * 2;
                float h0 = v.x + b1[n0];
                float h1 = v.y + b1[n0 + 1];
                h0 = h0 > 0.f ? h0 : 0.f;
                h1 = h1 > 0.f ? h1 : 0.f;
                s += h0 * w2[n0] + h1 * w2[n0 + 1];
            }
            red[rowOff + r][wn * 8 + ln] = s;
        }
        __syncthreads();
        if (tid < MT) {
            float s = 0.f;
            #pragma unroll
            for (int i = 0; i < 16; ++i) s += red[tid][i];
            rowAcc += s;
        }
        __syncthreads();
    }

    if (tid < MT) g_part[yy][mBase + tid] = rowAcc;
}

__global__ void scan_kernel(const float* __restrict__ bb2,
                            const float* __restrict__ br2,
                            float* __restrict__ out)
{
    const int tid = threadIdx.x;
    const float cb = bb2[0];
    const float cr = br2[0];

    // Phase 1: finalize logits (deterministic fixed-order sum), soft out + scan inputs
    for (int m = tid; m < M_TOT; m += 256) {
        float lb = ((g_part[0][m] + g_part[1][m]) + (g_part[2][m] + g_part[3][m])) + cb;
        float lr = ((g_part[4][m] + g_part[5][m]) + (g_part[6][m] + g_part[7][m])) + cr;
        int t = m >> 2;
        int b = m & 3;
        out[b * T_DIM + t] = lb;            // soft_boundaries[B,T]
        g_x[m]  = lb;
        g_rm[m] = (lr > 0.f) ? 1 : 0;       // sigmoid(lr) > 0.5  <=>  lr > 0
    }
    __syncthreads();

    // Phase 2: sequential LIF scan, one lane per batch element
    if (tid < B_DIM) {
        const int b = tid;
        float v = 0.f;
        float* __restrict__ hard = out + M_TOT + b * T_DIM;
        #pragma unroll 4
        for (int t = 0; t < T_DIM; ++t) {
            float x  = g_x[t * B_DIM + b];
            int   rm = g_rm[t * B_DIM + b];
            // v = v + (x - v)/TAU   (TAU=2, V_RESET=0), contraction blocked
            float d = __fmul_rn(__fsub_rn(x, v), 0.5f);
            v = __fadd_rn(v, d);
            float sp = (v >= 1.f) ? 1.f : 0.f;   // heaviside forward
            hard[t] = sp;
            if (sp != 0.f || rm) v = 0.f;        // hard reset + forced reset
        }
    }
}

extern "C" void kernel_launch(void* const* d_in, const int* in_sizes, int n_in,
                              void* d_out, int out_size)
{
    const float* hidden = (const float*)d_in[0];
    const float* Wb1    = (const float*)d_in[1];
    const float* bb1    = (const float*)d_in[2];
    const float* Wb2    = (const float*)d_in[3];
    const float* bb2    = (const float*)d_in[4];
    const float* Wr1    = (const float*)d_in[5];
    const float* br1    = (const float*)d_in[6];
    const float* Wr2    = (const float*)d_in[7];
    const float* br2    = (const float*)d_in[8];
    float* out = (float*)d_out;

    dim3 grid(M_TOT / MT, 8);   // 128 M-tiles x (2 MLPs x 4 N-quarters)
    mlp_gemm_kernel<<<grid, 256>>>(hidden, Wb1, bb1, Wb2, Wr1, br1, Wr2);
    scan_kernel<<<1, 256>>>(bb2, br2, out);
}

// round 6
// speedup vs baseline: 1.5765x; 1.5765x over previous
#include <cuda_runtime.h>

#define T_DIM 4096
#define B_DIM 4
#define D_DIM 1024
#define H_DIM 4096
#define M_TOT (T_DIM * B_DIM)   // 16384

#define MT 128                  // M tile per block
#define NT 128                  // N tile per chunk
#define KC 16                   // K chunk
#define KB_ITERS (D_DIM / KC)   // 64
#define NCHUNK 8                // 8 * 128 = 1024 N-cols per block

// Scratch (static __device__: allocation-free per harness rules)
__device__ float g_part[8][M_TOT];  // [mlp*4 + quarter][m] partial logits
__device__ float g_x[M_TOT];        // boundary logits (scan input)
__device__ int   g_rm[M_TOT];       // reset mask

__device__ __forceinline__ unsigned long long pack2(float x) {
    unsigned long long r;
    asm("mov.b64 %0, {%1, %2};" : "=l"(r) : "f"(x), "f"(x));
    return r;
}
__device__ __forceinline__ void fma2(unsigned long long& d,
                                     unsigned long long a,
                                     unsigned long long b) {
    asm("fma.rn.f32x2 %0, %1, %2, %0;" : "+l"(d) : "l"(a), "l"(b));
}
__device__ __forceinline__ float2 unpack2(unsigned long long v) {
    float lo, hi;
    asm("mov.b64 {%0, %1}, %2;" : "=f"(lo), "=f"(hi) : "l"(v));
    return make_float2(lo, hi);
}

__global__ void __launch_bounds__(256, 2)
mlp_gemm_kernel(const float* __restrict__ X,
                const float* __restrict__ Wb1, const float* __restrict__ bb1,
                const float* __restrict__ Wb2,
                const float* __restrict__ Wr1, const float* __restrict__ br1,
                const float* __restrict__ Wr2)
{
    __shared__ __align__(16) float Xs[2][KC * MT];
    __shared__ __align__(16) float Ws[2][KC * NT];
    __shared__ __align__(16) float red[MT][17];   // padded: no bank conflicts

    const int tid   = threadIdx.x;
    const int mBase = blockIdx.x * MT;
    const int yy    = blockIdx.y;      // 0..7: {mlp, quarter}
    const int mlp   = yy >> 2;
    const int q     = yy & 3;

    const float* __restrict__ W1 = mlp ? Wr1 : Wb1;
    const float* __restrict__ b1 = mlp ? br1 : bb1;
    const float* __restrict__ w2 = mlp ? Wr2 : Wb2;

    // warp tiling: 8 warps = 4 (M) x 2 (N); warp tile = 32 rows x 64 cols
    const int wid  = tid >> 5;
    const int lane = tid & 31;
    const int wm   = wid & 3;
    const int wn   = wid >> 2;
    const int lm   = lane & 3;
    const int ln   = lane >> 2;
    const int rowOff = wm * 32 + lm * 8;   // 8 rows per thread
    const int colOff = wn * 64 + ln * 8;   // 8 cols per thread

    // global-load assignments
    const int xRow = tid >> 1;             // 0..127
    const int xK0  = (tid & 1) * 8;        // k offset 0 or 8
    const int wK0  = tid >> 5;             // 0..7
    const int wCol = (tid & 31) * 4;

    const float* __restrict__ Xg = X + (size_t)mBase * D_DIM;

    float rowAcc = 0.f;                    // valid for tid < 128

    for (int nc = 0; nc < NCHUNK; ++nc) {
        const int nBase = q * 1024 + nc * NT;
        const float* __restrict__ Wg = W1 + nBase;

        unsigned long long acc[8][4];
        #pragma unroll
        for (int r = 0; r < 8; ++r)
            #pragma unroll
            for (int c = 0; c < 4; ++c) acc[r][c] = 0ULL;

        // prologue: fetch kb=0, stage into buffer 0
        float4 xv0 = *(const float4*)&Xg[xRow * D_DIM + xK0];
        float4 xv1 = *(const float4*)&Xg[xRow * D_DIM + xK0 + 4];
        float4 wv0 = *(const float4*)&Wg[(size_t)(wK0)     * H_DIM + wCol];
        float4 wv1 = *(const float4*)&Wg[(size_t)(wK0 + 8) * H_DIM + wCol];
        {
            float* xs = Xs[0];
            xs[(xK0 + 0) * MT + xRow] = xv0.x;
            xs[(xK0 + 1) * MT + xRow] = xv0.y;
            xs[(xK0 + 2) * MT + xRow] = xv0.z;
            xs[(xK0 + 3) * MT + xRow] = xv0.w;
            xs[(xK0 + 4) * MT + xRow] = xv1.x;
            xs[(xK0 + 5) * MT + xRow] = xv1.y;
            xs[(xK0 + 6) * MT + xRow] = xv1.z;
            xs[(xK0 + 7) * MT + xRow] = xv1.w;
            *(float4*)&Ws[0][(wK0)     * NT + wCol] = wv0;
            *(float4*)&Ws[0][(wK0 + 8) * NT + wCol] = wv1;
        }
        __syncthreads();

        for (int kb = 0; kb < KB_ITERS; ++kb) {
            const int cur = kb & 1;
            if (kb + 1 < KB_ITERS) {        // issue next tile's LDGs early
                const int kn = (kb + 1) * KC;
                xv0 = *(const float4*)&Xg[xRow * D_DIM + kn + xK0];
                xv1 = *(const float4*)&Xg[xRow * D_DIM + kn + xK0 + 4];
                wv0 = *(const float4*)&Wg[(size_t)(kn + wK0)     * H_DIM + wCol];
                wv1 = *(const float4*)&Wg[(size_t)(kn + wK0 + 8) * H_DIM + wCol];
            }

            const float* xs = Xs[cur];
            const float* ws = Ws[cur];
            #pragma unroll
            for (int k = 0; k < KC; ++k) {
                float4 a0 = *(const float4*)&xs[k * MT + rowOff];
                float4 a1 = *(const float4*)&xs[k * MT + rowOff + 4];
                ulonglong2 bq0 = *(const ulonglong2*)&ws[k * NT + colOff];
                ulonglong2 bq1 = *(const ulonglong2*)&ws[k * NT + colOff + 4];
                unsigned long long bp0 = bq0.x, bp1 = bq0.y, bp2 = bq1.x, bp3 = bq1.y;
                float a[8] = {a0.x, a0.y, a0.z, a0.w, a1.x, a1.y, a1.z, a1.w};
                #pragma unroll
                for (int r = 0; r < 8; ++r) {
                    unsigned long long ap = pack2(a[r]);
                    fma2(acc[r][0], ap, bp0);
                    fma2(acc[r][1], ap, bp1);
                    fma2(acc[r][2], ap, bp2);
                    fma2(acc[r][3], ap, bp3);
                }
            }

            if (kb + 1 < KB_ITERS) {        // stage next tile
                float* xs2 = Xs[cur ^ 1];
                xs2[(xK0 + 0) * MT + xRow] = xv0.x;
                xs2[(xK0 + 1) * MT + xRow] = xv0.y;
                xs2[(xK0 + 2) * MT + xRow] = xv0.z;
                xs2[(xK0 + 3) * MT + xRow] = xv0.w;
                xs2[(xK0 + 4) * MT + xRow] = xv1.x;
                xs2[(xK0 + 5) * MT + xRow] = xv1.y;
                xs2[(xK0 + 6) * MT + xRow] = xv1.z;
                xs2[(xK0 + 7) * MT + xRow] = xv1.w;
                *(float4*)&Ws[cur ^ 1][(wK0)     * NT + wCol] = wv0;
                *(float4*)&Ws[cur ^ 1][(wK0 + 8) * NT + wCol] = wv1;
            }
            __syncthreads();
        }

        // epilogue: ReLU + dot(w2), deterministic tree reduce across 16 col-threads
        #pragma unroll
        for (int r = 0; r < 8; ++r) {
            float s = 0.f;
            #pragma unroll
            for (int c = 0; c < 4; ++c) {
                float2 v = unpack2(acc[r][c]);
                int n0 = nBase + colOff + c * 2;
                float h0 = v.x + b1[n0];
                float h1 = v.y + b1[n0 + 1];
                h0 = h0 > 0.f ? h0 : 0.f;
                h1 = h1 > 0.f ? h1 : 0.f;
                s += h0 * w2[n0] + h1 * w2[n0 + 1];
            }
            red[rowOff + r][wn * 8 + ln] = s;
        }
        __syncthreads();
        if (tid < MT) {
            float s = 0.f;
            #pragma unroll
            for (int i = 0; i < 16; ++i) s += red[tid][i];
            rowAcc += s;
        }
        __syncthreads();
    }

    if (tid < MT) g_part[yy][mBase + tid] = rowAcc;
}

__global__ void scan_kernel(const float* __restrict__ bb2,
                            const float* __restrict__ br2,
                            float* __restrict__ out)
{
    const int tid = threadIdx.x;
    const float cb = bb2[0];
    const float cr = br2[0];

    // Phase 1: finalize logits (deterministic fixed-order sum), soft out + scan inputs
    for (int m = tid; m < M_TOT; m += 256) {
        float lb = ((g_part[0][m] + g_part[1][m]) + (g_part[2][m] + g_part[3][m])) + cb;
        float lr = ((g_part[4][m] + g_part[5][m]) + (g_part[6][m] + g_part[7][m])) + cr;
        int t = m >> 2;
        int b = m & 3;
        out[b * T_DIM + t] = lb;            // soft_boundaries[B,T]
        g_x[m]  = lb;
        g_rm[m] = (lr > 0.f) ? 1 : 0;       // sigmoid(lr) > 0.5  <=>  lr > 0
    }
    __syncthreads();

    // Phase 2: sequential LIF scan, one lane per batch element
    if (tid < B_DIM) {
        const int b = tid;
        float v = 0.f;
        float* __restrict__ hard = out + M_TOT + b * T_DIM;
        #pragma unroll 4
        for (int t = 0; t < T_DIM; ++t) {
            float x  = g_x[t * B_DIM + b];
            int   rm = g_rm[t * B_DIM + b];
            // v = v + (x - v)/TAU   (TAU=2, V_RESET=0), contraction blocked
            float d = __fmul_rn(__fsub_rn(x, v), 0.5f);
            v = __fadd_rn(v, d);
            float sp = (v >= 1.f) ? 1.f : 0.f;   // heaviside forward
            hard[t] = sp;
            if (sp != 0.f || rm) v = 0.f;        // hard reset + forced reset
        }
    }
}

extern "C" void kernel_launch(void* const* d_in, const int* in_sizes, int n_in,
                              void* d_out, int out_size)
{
    const float* hidden = (const float*)d_in[0];
    const float* Wb1    = (const float*)d_in[1];
    const float* bb1    = (const float*)d_in[2];
    const float* Wb2    = (const float*)d_in[3];
    const float* bb2    = (const float*)d_in[4];
    const float* Wr1    = (const float*)d_in[5];
    const float* br1    = (const float*)d_in[6];
    const float* Wr2    = (const float*)d_in[7];
    const float* br2    = (const float*)d_in[8];
    float* out = (float*)d_out;

    dim3 grid(M_TOT / MT, 8);   // 128 M-tiles x (2 MLPs x 4 N-quarters)
    mlp_gemm_kernel<<<grid, 256>>>(hidden, Wb1, bb1, Wb2, Wr1, br1, Wr2);
    scan_kernel<<<1, 256>>>(bb2, br2, out);
}

// round 9
// speedup vs baseline: 1.5766x; 1.0000x over previous
#include <cuda_runtime.h>

#define T_DIM 4096
#define B_DIM 4
#define D_DIM 1024
#define H_DIM 4096
#define M_TOT (T_DIM * B_DIM)   // 16384

#define MT 128                  // M tile per block
#define NT 128                  // N tile per chunk
#define KC 16                   // K chunk
#define KB_ITERS (D_DIM / KC)   // 64
#define NCHUNK 8                // 8 * 128 = 1024 N-cols per block

// Scratch (static __device__: allocation-free per harness rules)
__device__ float g_part[8][M_TOT];  // [mlp*4 + quarter][m] partial logits
__device__ float g_x[M_TOT];        // boundary logits (scan input)
__device__ int   g_rm[M_TOT];       // reset mask

__device__ __forceinline__ unsigned long long pack2(float x) {
    unsigned long long r;
    asm("mov.b64 %0, {%1, %2};" : "=l"(r) : "f"(x), "f"(x));
    return r;
}
__device__ __forceinline__ void fma2(unsigned long long& d,
                                     unsigned long long a,
                                     unsigned long long b) {
    asm("fma.rn.f32x2 %0, %1, %2, %0;" : "+l"(d) : "l"(a), "l"(b));
}
__device__ __forceinline__ float2 unpack2(unsigned long long v) {
    float lo, hi;
    asm("mov.b64 {%0, %1}, %2;" : "=f"(lo), "=f"(hi) : "l"(v));
    return make_float2(lo, hi);
}

__global__ void __launch_bounds__(256, 2)
mlp_gemm_kernel(const float* __restrict__ X,
                const float* __restrict__ Wb1, const float* __restrict__ bb1,
                const float* __restrict__ Wb2,
                const float* __restrict__ Wr1, const float* __restrict__ br1,
                const float* __restrict__ Wr2)
{
    __shared__ __align__(16) float Xs[2][KC * MT];
    __shared__ __align__(16) float Ws[2][KC * NT];
    __shared__ __align__(16) float red[MT][17];   // padded: no bank conflicts

    const int tid   = threadIdx.x;
    const int mBase = blockIdx.x * MT;
    const int yy    = blockIdx.y;      // 0..7: {mlp, quarter}
    const int mlp   = yy >> 2;
    const int q     = yy & 3;

    const float* __restrict__ W1 = mlp ? Wr1 : Wb1;
    const float* __restrict__ b1 = mlp ? br1 : bb1;
    const float* __restrict__ w2 = mlp ? Wr2 : Wb2;

    // warp tiling: 8 warps = 4 (M) x 2 (N); warp tile = 32 rows x 64 cols
    const int wid  = tid >> 5;
    const int lane = tid & 31;
    const int wm   = wid & 3;
    const int wn   = wid >> 2;
    const int lm   = lane & 3;
    const int ln   = lane >> 2;
    const int rowOff = wm * 32 + lm * 8;   // 8 rows per thread
    const int colOff = wn * 64 + ln * 8;   // 8 cols per thread

    // global-load assignments
    const int xRow = tid >> 1;             // 0..127
    const int xK0  = (tid & 1) * 8;        // k offset 0 or 8
    const int wK0  = tid >> 5;             // 0..7
    const int wCol = (tid & 31) * 4;

    const float* __restrict__ Xg = X + (size_t)mBase * D_DIM;

    float rowAcc = 0.f;                    // valid for tid < 128

    for (int nc = 0; nc < NCHUNK; ++nc) {
        const int nBase = q * 1024 + nc * NT;
        const float* __restrict__ Wg = W1 + nBase;

        unsigned long long acc[8][4];
        #pragma unroll
        for (int r = 0; r < 8; ++r)
            #pragma unroll
            for (int c = 0; c < 4; ++c) acc[r][c] = 0ULL;

        // prologue: fetch kb=0, stage into buffer 0
        float4 xv0 = *(const float4*)&Xg[xRow * D_DIM + xK0];
        float4 xv1 = *(const float4*)&Xg[xRow * D_DIM + xK0 + 4];
        float4 wv0 = *(const float4*)&Wg[(size_t)(wK0)     * H_DIM + wCol];
        float4 wv1 = *(const float4*)&Wg[(size_t)(wK0 + 8) * H_DIM + wCol];
        {
            float* xs = Xs[0];
            xs[(xK0 + 0) * MT + xRow] = xv0.x;
            xs[(xK0 + 1) * MT + xRow] = xv0.y;
            xs[(xK0 + 2) * MT + xRow] = xv0.z;
            xs[(xK0 + 3) * MT + xRow] = xv0.w;
            xs[(xK0 + 4) * MT + xRow] = xv1.x;
            xs[(xK0 + 5) * MT + xRow] = xv1.y;
            xs[(xK0 + 6) * MT + xRow] = xv1.z;
            xs[(xK0 + 7) * MT + xRow] = xv1.w;
            *(float4*)&Ws[0][(wK0)     * NT + wCol] = wv0;
            *(float4*)&Ws[0][(wK0 + 8) * NT + wCol] = wv1;
        }
        __syncthreads();

        for (int kb = 0; kb < KB_ITERS; ++kb) {
            const int cur = kb & 1;
            if (kb + 1 < KB_ITERS) {        // issue next tile's LDGs early
                const int kn = (kb + 1) * KC;
                xv0 = *(const float4*)&Xg[xRow * D_DIM + kn + xK0];
                xv1 = *(const float4*)&Xg[xRow * D_DIM + kn + xK0 + 4];
                wv0 = *(const float4*)&Wg[(size_t)(kn + wK0)     * H_DIM + wCol];
                wv1 = *(const float4*)&Wg[(size_t)(kn + wK0 + 8) * H_DIM + wCol];
            }

            const float* xs = Xs[cur];
            const float* ws = Ws[cur];
            #pragma unroll
            for (int k = 0; k < KC; ++k) {
                float4 a0 = *(const float4*)&xs[k * MT + rowOff];
                float4 a1 = *(const float4*)&xs[k * MT + rowOff + 4];
                ulonglong2 bq0 = *(const ulonglong2*)&ws[k * NT + colOff];
                ulonglong2 bq1 = *(const ulonglong2*)&ws[k * NT + colOff + 4];
                unsigned long long bp0 = bq0.x, bp1 = bq0.y, bp2 = bq1.x, bp3 = bq1.y;
                float a[8] = {a0.x, a0.y, a0.z, a0.w, a1.x, a1.y, a1.z, a1.w};
                #pragma unroll
                for (int r = 0; r < 8; ++r) {
                    unsigned long long ap = pack2(a[r]);
                    fma2(acc[r][0], ap, bp0);
                    fma2(acc[r][1], ap, bp1);
                    fma2(acc[r][2], ap, bp2);
                    fma2(acc[r][3], ap, bp3);
                }
            }

            if (kb + 1 < KB_ITERS) {        // stage next tile
                float* xs2 = Xs[cur ^ 1];
                xs2[(xK0 + 0) * MT + xRow] = xv0.x;
                xs2[(xK0 + 1) * MT + xRow] = xv0.y;
                xs2[(xK0 + 2) * MT + xRow] = xv0.z;
                xs2[(xK0 + 3) * MT + xRow] = xv0.w;
                xs2[(xK0 + 4) * MT + xRow] = xv1.x;
                xs2[(xK0 + 5) * MT + xRow] = xv1.y;
                xs2[(xK0 + 6) * MT + xRow] = xv1.z;
                xs2[(xK0 + 7) * MT + xRow] = xv1.w;
                *(float4*)&Ws[cur ^ 1][(wK0)     * NT + wCol] = wv0;
                *(float4*)&Ws[cur ^ 1][(wK0 + 8) * NT + wCol] = wv1;
            }
            __syncthreads();
        }

        // epilogue: ReLU + dot(w2), deterministic tree reduce across 16 col-threads
        #pragma unroll
        for (int r = 0; r < 8; ++r) {
            float s = 0.f;
            #pragma unroll
            for (int c = 0; c < 4; ++c) {
                float2 v = unpack2(acc[r][c]);
                int n0 = nBase + colOff + c * 2;
                float h0 = v.x + b1[n0];
                float h1 = v.y + b1[n0 + 1];
                h0 = h0 > 0.f ? h0 : 0.f;
                h1 = h1 > 0.f ? h1 : 0.f;
                s += h0 * w2[n0] + h1 * w2[n0 + 1];
            }
            red[rowOff + r][wn * 8 + ln] = s;
        }
        __syncthreads();
        if (tid < MT) {
            float s = 0.f;
            #pragma unroll
            for (int i = 0; i < 16; ++i) s += red[tid][i];
            rowAcc += s;
        }
        __syncthreads();
    }

    if (tid < MT) g_part[yy][mBase + tid] = rowAcc;
}

__global__ void scan_kernel(const float* __restrict__ bb2,
                            const float* __restrict__ br2,
                            float* __restrict__ out)
{
    const int tid = threadIdx.x;
    const float cb = bb2[0];
    const float cr = br2[0];

    // Phase 1: finalize logits (deterministic fixed-order sum), soft out + scan inputs
    for (int m = tid; m < M_TOT; m += 256) {
        float lb = ((g_part[0][m] + g_part[1][m]) + (g_part[2][m] + g_part[3][m])) + cb;
        float lr = ((g_part[4][m] + g_part[5][m]) + (g_part[6][m] + g_part[7][m])) + cr;
        int t = m >> 2;
        int b = m & 3;
        out[b * T_DIM + t] = lb;            // soft_boundaries[B,T]
        g_x[m]  = lb;
        g_rm[m] = (lr > 0.f) ? 1 : 0;       // sigmoid(lr) > 0.5  <=>  lr > 0
    }
    __syncthreads();

    // Phase 2: sequential LIF scan, one lane per batch element
    if (tid < B_DIM) {
        const int b = tid;
        float v = 0.f;
        float* __restrict__ hard = out + M_TOT + b * T_DIM;
        #pragma unroll 4
        for (int t = 0; t < T_DIM; ++t) {
            float x  = g_x[t * B_DIM + b];
            int   rm = g_rm[t * B_DIM + b];
            // v = v + (x - v)/TAU   (TAU=2, V_RESET=0), contraction blocked
            float d = __fmul_rn(__fsub_rn(x, v), 0.5f);
            v = __fadd_rn(v, d);
            float sp = (v >= 1.f) ? 1.f : 0.f;   // heaviside forward
            hard[t] = sp;
            if (sp != 0.f || rm) v = 0.f;        // hard reset + forced reset
        }
    }
}

extern "C" void kernel_launch(void* const* d_in, const int* in_sizes, int n_in,
                              void* d_out, int out_size)
{
    const float* hidden = (const float*)d_in[0];
    const float* Wb1    = (const float*)d_in[1];
    const float* bb1    = (const float*)d_in[2];
    const float* Wb2    = (const float*)d_in[3];
    const float* bb2    = (const float*)d_in[4];
    const float* Wr1    = (const float*)d_in[5];
    const float* br1    = (const float*)d_in[6];
    const float* Wr2    = (const float*)d_in[7];
    const float* br2    = (const float*)d_in[8];
    float* out = (float*)d_out;

    dim3 grid(M_TOT / MT, 8);   // 128 M-tiles x (2 MLPs x 4 N-quarters)
    mlp_gemm_kernel<<<grid, 256>>>(hidden, Wb1, bb1, Wb2, Wr1, br1, Wr2);
    scan_kernel<<<1, 256>>>(bb2, br2, out);
}